// round 16
// baseline (speedup 1.0000x reference)
#include <cuda_runtime.h>
#include <cuda_bf16.h>
#include <math.h>

#define BB    8
#define TENC  512
#define DIN   512
#define TDEC  150
#define ODIM  80
#define DRNN  1024
#define PRE   256
#define ATTN  128
#define LOC   32
#define KF    31
#define N1    84
#define N2    64

// smem float offsets
#define OFF_P     16384          // 512 partials
#define OFF_H0S   16896          // 32 h0 stash
#define OFF_ACON  16928          // Wl 4096 | flt 992 | vv 128
#define SMEM_FLOATS (OFF_ACON + 5216)

// ---------------- device scratch ----------------
__device__ __align__(16) float g_pm[BB * TENC * ATTN];
__device__ __align__(16) float g_e[BB * TENC];
__device__ __align__(16) float g_attcum[BB * TENC];
__device__ __align__(16) float g_attc[BB * TDEC * DIN];
__device__ __align__(16) float g_p2[BB * TDEC * PRE];
__device__ __align__(16) float g_qp[256 * BB * ATTN];   // per-C-unit q partials
__device__ __align__(16) float g_h0[2][BB * DRNN];
__device__ __align__(16) float g_c0[2][BB * DRNN];
__device__ __align__(16) float g_h1[2][BB * DRNN];
__device__ __align__(16) float g_c1[2][BB * DRNN];

__device__ unsigned g_bar1_count = 0, g_bar1_gen = 0;
__device__ unsigned g_bar2_count = 0, g_bar2_gen = 0;
__device__ unsigned g_c_done = 0, g_e_done = 0;

// ---------------- helpers ----------------
__device__ __forceinline__ float warp_sum(float v) {
    #pragma unroll
    for (int o = 16; o; o >>= 1) v += __shfl_down_sync(0xffffffffu, v, o);
    return v;
}
__device__ __forceinline__ float sigm(float x) { return 1.0f / (1.0f + __expf(-x)); }
__device__ __forceinline__ float tanh_f(float x) {
    float xc = fminf(fmaxf(x, -10.0f), 10.0f);
    float e = __expf(2.0f * xc);
    return __fdividef(e - 1.0f, e + 1.0f);
}
__device__ __forceinline__ float tanh_hw(float x) {
    float y;
    asm("tanh.approx.f32 %0, %1;" : "=f"(y) : "f"(x));
    return y;
}

__device__ __forceinline__ void group_sync(unsigned* cnt, unsigned* gen, unsigned n) {
    __syncthreads();
    if (threadIdx.x == 0) {
        __threadfence();
        unsigned g = *(volatile unsigned*)gen;
        if (atomicAdd(cnt, 1u) == n - 1) {
            atomicExch(cnt, 0u);
            __threadfence();
            atomicExch(gen, g + 1u);
        } else {
            while (*(volatile unsigned*)gen == g) {}
        }
    }
    __syncthreads();
}
__device__ __forceinline__ void wait_ge(unsigned* v, unsigned target) {
    __syncthreads();
    if (threadIdx.x == 0) {
        while (*(volatile unsigned*)v < target) {}
        __threadfence();
    }
    __syncthreads();
}

// ---------------- init ----------------
__global__ void init_kernel() {
    int i = blockIdx.x * 256 + threadIdx.x;
    if (i < BB * DRNN) {
        g_h0[0][i] = 0.f; g_h0[1][i] = 0.f;
        g_c0[0][i] = 0.f; g_c0[1][i] = 0.f;
        g_h1[0][i] = 0.f; g_h1[1][i] = 0.f;
        g_c1[0][i] = 0.f; g_c1[1][i] = 0.f;
    }
    if (i < BB * TENC) g_attcum[i] = 0.f;
    if (i < 256 * BB * ATTN) g_qp[i] = 0.f;
    if (i == 0) { g_c_done = 0; g_e_done = 0; }
}

// ---------------- processed memory ----------------
__global__ __launch_bounds__(256) void pm_kernel(const float* __restrict__ mem,
                                                 const float* __restrict__ Wmem) {
    int b = blockIdx.x >> 6;
    int t0 = (blockIdx.x & 63) * 8;
    __shared__ __align__(16) float smb[8 * DIN];
    const float* mptr = mem + ((size_t)b * TENC + t0) * DIN;
    for (int i = threadIdx.x; i < 8 * DIN; i += 256) smb[i] = mptr[i];
    __syncthreads();
    int w = threadIdx.x >> 5, ln = threadIdx.x & 31;
    for (int ai = 0; ai < 16; ai++) {
        int a = w * 16 + ai;
        const float4* wr = (const float4*)(Wmem + (size_t)a * DIN);
        float acc[8] = {0,0,0,0,0,0,0,0};
        #pragma unroll
        for (int it = 0; it < 4; it++) {
            float4 wv = wr[ln + it * 32];
            #pragma unroll
            for (int t = 0; t < 8; t++) {
                float4 hv = *(const float4*)(smb + t * DIN + (ln + it * 32) * 4);
                acc[t] += wv.x*hv.x + wv.y*hv.y + wv.z*hv.z + wv.w*hv.w;
            }
        }
        #pragma unroll
        for (int t = 0; t < 8; t++) {
            float v = warp_sum(acc[t]);
            if (ln == 0) g_pm[((size_t)(b * TENC) + (t0 + t)) * ATTN + a] = v;
        }
    }
}

// ---------------- prenet ----------------
__global__ __launch_bounds__(256) void prenet_kernel(const float* __restrict__ tgt,
        const float* __restrict__ W1, const float* __restrict__ b1,
        const float* __restrict__ W2, const float* __restrict__ b2) {
    int b = blockIdx.x / TDEC, s = blockIdx.x % TDEC;
    __shared__ float prev[80];
    __shared__ float p1s[PRE];
    int tid = threadIdx.x;
    if (tid < 80) prev[tid] = (s == 0) ? 0.f : tgt[((size_t)b * TDEC + (s - 1)) * ODIM + tid];
    __syncthreads();
    int w = tid >> 5, ln = tid & 31;
    for (int oi = 0; oi < 32; oi++) {
        int o = w * 32 + oi;
        float acc = 0.f;
        int k = ln * 4;
        if (k < 80) {
            float4 wv = *(const float4*)(W1 + (size_t)o * 80 + k);
            acc = wv.x*prev[k] + wv.y*prev[k+1] + wv.z*prev[k+2] + wv.w*prev[k+3];
        }
        acc = warp_sum(acc);
        if (ln == 0) p1s[o] = fmaxf(acc + b1[o], 0.f);
    }
    __syncthreads();
    for (int oi = 0; oi < 32; oi++) {
        int o = w * 32 + oi;
        float acc = 0.f;
        #pragma unroll
        for (int it = 0; it < 2; it++) {
            int k = ln * 4 + it * 128;
            float4 wv = *(const float4*)(W2 + (size_t)o * PRE + k);
            acc += wv.x*p1s[k] + wv.y*p1s[k+1] + wv.z*p1s[k+2] + wv.w*p1s[k+3];
        }
        acc = warp_sum(acc);
        if (ln == 0) g_p2[((size_t)b * TDEC + s) * PRE + o] = fmaxf(acc + b2[o], 0.f);
    }
}

// ---------------- out/stop projection (warp per (col,b)) ----------------
__device__ __forceinline__ void outstop_warp(int col, int b, int sprev, int h1buf, int ln,
        const float* __restrict__ featW, const float* __restrict__ stopW,
        const float* __restrict__ stopb, float* __restrict__ out) {
    const float4* wr = (const float4*)((col < ODIM) ? (featW + (size_t)col * 1536) : stopW);
    const float4* h1p = (const float4*)(g_h1[h1buf] + b * DRNN);
    const float4* acp = (const float4*)(g_attc + ((size_t)(b * TDEC) + sprev) * DIN);
    float acc = 0.f;
    #pragma unroll
    for (int it = 0; it < 8; it++) {
        float4 wv = wr[ln + it * 32];
        float4 zv = h1p[ln + it * 32];
        acc += wv.x*zv.x + wv.y*zv.y + wv.z*zv.z + wv.w*zv.w;
    }
    #pragma unroll
    for (int it = 0; it < 4; it++) {
        float4 wv = wr[256 + ln + it * 32];
        float4 zv = acp[ln + it * 32];
        acc += wv.x*zv.x + wv.y*zv.y + wv.z*zv.z + wv.w*zv.w;
    }
    acc = warp_sum(acc);
    if (ln == 0) {
        if (col < ODIM) out[((size_t)(b * TDEC) + sprev) * ODIM + col] = acc;
        else            out[BB * TDEC * ODIM + b * TDEC + sprev] = acc + stopb[0];
    }
}

// ---------------- persistent decoder ----------------
__global__ __launch_bounds__(512) void decoder_persistent(
        const float* __restrict__ mem, const int* __restrict__ mlen,
        const float* __restrict__ Wq, const float* __restrict__ Wloc,
        const float* __restrict__ filt, const float* __restrict__ av,
        const float* __restrict__ ab,
        const float* __restrict__ Wi0, const float* __restrict__ Wh0,
        const float* __restrict__ bl0,
        const float* __restrict__ Wi1, const float* __restrict__ Wh1,
        const float* __restrict__ bl1,
        const float* __restrict__ featW, const float* __restrict__ stopW,
        const float* __restrict__ stopb, float* __restrict__ out)
{
    extern __shared__ __align__(16) float sm[];
    const int bid = blockIdx.x, tid = threadIdx.x;
    const int w = tid >> 5, ln = tid & 31;

    if (bid < N1) {
        // ================= CHAIN 1: A -> B -> C per step =================
        {   // loop-invariant attention constants
            float* Wl  = sm + OFF_ACON;
            float* flt = sm + OFF_ACON + 4096;
            float* vv  = sm + OFF_ACON + 5088;
            for (int i = tid; i < 4096; i += 512) Wl[i] = Wloc[i];
            for (int i = tid; i < 992; i += 512) flt[i] = filt[i];
            if (tid < 128) vv[tid] = av[tid];
        }
        __syncthreads();

        for (int s = 0; s < TDEC; s++) {
            const int ep = s & 1;

            // ---- A(s): units (b, 32-t) ----
            int na_cnt = (bid >= 40) ? 2 : 1;
            for (int na = 0; na < na_cnt; na++) {
                int u = (na == 0) ? bid : (84 + (bid - 40));
                if (u >= 128) continue;
                __syncthreads();
                const int b = u >> 4, t0 = (u & 15) * 32;
                float* qs   = sm;
                float* part = sm + 128;
                float* fs   = sm + 640;
                float* cum  = sm + 1696;
                float* eps  = sm + 1760;
                const float* Wl  = sm + OFF_ACON;
                const float* flt = sm + OFF_ACON + 4096;
                const float* vv  = sm + OFF_ACON + 5088;
                {
                    int a = tid & 127, qtr = tid >> 7;
                    float accq = 0.f;
                    #pragma unroll 4
                    for (int blk = qtr * 64; blk < qtr * 64 + 64; blk++)
                        accq += g_qp[blk * 1024 + b * 128 + a];
                    part[qtr * 128 + a] = accq;
                }
                if (tid < 64) {
                    int t = t0 - 15 + tid;
                    cum[tid] = (t >= 0 && t < TENC) ? g_attcum[b * TENC + t] : 0.f;
                }
                __syncthreads();
                if (tid < 128)
                    qs[tid] = part[tid] + part[128 + tid] + part[256 + tid] + part[384 + tid] + ab[tid];
                __syncthreads();
                #pragma unroll
                for (int hf = 0; hf < 2; hf++) {
                    int c = w + hf * 16;
                    float f = 0.f;
                    #pragma unroll
                    for (int k = 0; k < KF; k++) f += cum[ln + k] * flt[c * KF + k];
                    fs[ln * 33 + c] = f;
                }
                __syncthreads();
                float accA[8];
                #pragma unroll
                for (int i = 0; i < 8; i++) accA[i] = 0.f;
                #pragma unroll 4
                for (int c = 0; c < 32; c++) {
                    float fv = fs[ln * 33 + c];
                    #pragma unroll
                    for (int i = 0; i < 8; i++)
                        accA[i] += fv * Wl[(w * 8 + i) * 32 + c];
                }
                const float4* pmp = (const float4*)(g_pm + ((size_t)(b * TENC) + t0 + ln) * ATTN + w * 8);
                float ep_ = 0.f;
                #pragma unroll
                for (int v4 = 0; v4 < 2; v4++) {
                    float4 p = pmp[v4];
                    int a = w * 8 + v4 * 4;
                    ep_ += vv[a    ] * tanh_hw(p.x + accA[v4*4    ] + qs[a    ]);
                    ep_ += vv[a + 1] * tanh_hw(p.y + accA[v4*4 + 1] + qs[a + 1]);
                    ep_ += vv[a + 2] * tanh_hw(p.z + accA[v4*4 + 2] + qs[a + 2]);
                    ep_ += vv[a + 3] * tanh_hw(p.w + accA[v4*4 + 3] + qs[a + 3]);
                }
                eps[w * 32 + ln] = ep_;
                __syncthreads();
                if (w == 0) {
                    float e = 0.f;
                    #pragma unroll
                    for (int ww = 0; ww < 16; ww++) e += eps[ww * 32 + ln];
                    g_e[b * TENC + t0 + ln] = e;
                }
            }
            group_sync(&g_bar1_count, &g_bar1_gen, N1);

            // ---- B(s) on blocks 4..19 ----
            if (bid >= 4 && bid < 20) {
                const int bb = bid - 4;
                const int b = bb >> 1, half = bb & 1;
                float* wsm  = sm;
                float* red  = sm + 512;
                float4* ctx4 = (float4*)(sm + 528);
                int len = mlen[b];
                const float* epv = g_e + b * TENC;
                float e0 = (tid < len) ? epv[tid] : -1e9f;
                float mx = e0;
                #pragma unroll
                for (int o = 16; o; o >>= 1) mx = fmaxf(mx, __shfl_xor_sync(0xffffffffu, mx, o));
                if (ln == 0) red[w] = mx;
                __syncthreads();
                mx = red[0];
                #pragma unroll
                for (int ww = 1; ww < 16; ww++) mx = fmaxf(mx, red[ww]);
                float x0 = __expf(e0 - mx);
                float sw = warp_sum(x0);
                __syncthreads();
                if (ln == 0) red[w] = sw;
                __syncthreads();
                float S = 0.f;
                #pragma unroll
                for (int ww = 0; ww < 16; ww++) S += red[ww];
                float inv = __fdividef(1.0f, S);
                wsm[tid] = x0 * inv;
                __syncthreads();
                int tg = tid >> 6, dl = tid & 63;
                const float4* mp4 = (const float4*)(mem + ((size_t)b * TENC) * DIN + half * 256) + dl;
                float4 a = {0.f, 0.f, 0.f, 0.f};
                #pragma unroll 4
                for (int t = tg * 64; t < tg * 64 + 64; t++) {
                    float wv = wsm[t];
                    float4 m = mp4[(size_t)t * 128];
                    a.x += wv * m.x; a.y += wv * m.y; a.z += wv * m.z; a.w += wv * m.w;
                }
                ctx4[tg * 64 + dl] = a;
                __syncthreads();
                if (tid < 64) {
                    float4 sa = ctx4[tid];
                    #pragma unroll
                    for (int tg2 = 1; tg2 < 8; tg2++) {
                        float4 v = ctx4[tg2 * 64 + tid];
                        sa.x += v.x; sa.y += v.y; sa.z += v.z; sa.w += v.w;
                    }
                    *(float4*)(g_attc + ((size_t)(b * TDEC) + s) * DIN + half * 256 + tid * 4) = sa;
                }
                if (half == 0) {
                    float wv = wsm[tid];
                    out[BB * TDEC * ODIM + BB * TDEC + ((size_t)(b * TDEC) + s) * TENC + tid] = wv;
                    g_attcum[b * TENC + tid] += wv;
                }
            }
            group_sync(&g_bar1_count, &g_bar1_gen, N1);

            // ---- C(s): wait for E(s-2), then full LSTM0 ----
            if (s >= 2) wait_ge(&g_e_done, (unsigned)(s - 1));
            {
                float* xs = sm;  // [b][1792]
                float4* xs4 = (float4*)xs;
                const float4* h0_4 = (const float4*)(g_h0[ep]);
                for (int i = tid; i < 3584; i += 512) {
                    int b = i / 448, o = i - b * 448;
                    float4 v;
                    if (o < 128)      v = ((const float4*)(g_attc + ((size_t)(b * TDEC) + s) * DIN))[o];
                    else if (o < 192) v = ((const float4*)(g_p2 + ((size_t)(b * TDEC) + s) * PRE))[o - 128];
                    else              v = h0_4[b * 256 + (o - 192)];
                    xs4[i] = v;
                }
                __syncthreads();
                for (int nc = 0; nc < 4; nc++) {
                    int u;
                    if (nc == 0) u = bid;
                    else if (nc == 1) u = bid + 84;
                    else if (nc == 2) u = bid + 168;
                    else u = (bid < 4) ? bid + 252 : 9999;
                    if (u >= 256) continue;
                    int jl = w >> 2, q = w & 3;
                    int j = u * 4 + jl;
                    const float4 *w0, *w1, *w2, *w3;
                    int xo_base, its;
                    if (q < 2) {
                        int koff = q * 384;
                        w0 = (const float4*)(Wi0 + (size_t)(0 * 1024 + j) * 768 + koff);
                        w1 = (const float4*)(Wi0 + (size_t)(1 * 1024 + j) * 768 + koff);
                        w2 = (const float4*)(Wi0 + (size_t)(2 * 1024 + j) * 768 + koff);
                        w3 = (const float4*)(Wi0 + (size_t)(3 * 1024 + j) * 768 + koff);
                        xo_base = q * 384; its = 3;
                    } else {
                        int koff = (q - 2) * 512;
                        w0 = (const float4*)(Wh0 + (size_t)(0 * 1024 + j) * 1024 + koff);
                        w1 = (const float4*)(Wh0 + (size_t)(1 * 1024 + j) * 1024 + koff);
                        w2 = (const float4*)(Wh0 + (size_t)(2 * 1024 + j) * 1024 + koff);
                        w3 = (const float4*)(Wh0 + (size_t)(3 * 1024 + j) * 1024 + koff);
                        xo_base = 768 + (q - 2) * 512; its = 4;
                    }
                    float acc[4][8];
                    #pragma unroll
                    for (int g = 0; g < 4; g++)
                        #pragma unroll
                        for (int b = 0; b < 8; b++) acc[g][b] = 0.f;
                    for (int it = 0; it < its; it++) {
                        float4 wv0 = w0[it * 32 + ln];
                        float4 wv1 = w1[it * 32 + ln];
                        float4 wv2 = w2[it * 32 + ln];
                        float4 wv3 = w3[it * 32 + ln];
                        int xo = xo_base + it * 128 + ln * 4;
                        #pragma unroll
                        for (int b = 0; b < 8; b++) {
                            float4 xv = *(const float4*)(xs + b * 1792 + xo);
                            acc[0][b] += wv0.x*xv.x + wv0.y*xv.y + wv0.z*xv.z + wv0.w*xv.w;
                            acc[1][b] += wv1.x*xv.x + wv1.y*xv.y + wv1.z*xv.z + wv1.w*xv.w;
                            acc[2][b] += wv2.x*xv.x + wv2.y*xv.y + wv2.z*xv.z + wv2.w*xv.w;
                            acc[3][b] += wv3.x*xv.x + wv3.y*xv.y + wv3.z*xv.z + wv3.w*xv.w;
                        }
                    }
                    float* P = sm + OFF_P;
                    #pragma unroll
                    for (int g = 0; g < 4; g++)
                        #pragma unroll
                        for (int b = 0; b < 8; b++) {
                            float v = warp_sum(acc[g][b]);
                            if (ln == 0) P[(w * 4 + g) * 8 + b] = v;
                        }
                    __syncthreads();
                    if (tid < 32) {
                        float* h0s = sm + OFF_H0S;
                        int jl2 = tid >> 3, b = tid & 7, j2 = u * 4 + jl2;
                        float gv[4];
                        #pragma unroll
                        for (int g = 0; g < 4; g++)
                            gv[g] = P[((jl2*4+0)*4+g)*8+b] + P[((jl2*4+1)*4+g)*8+b]
                                  + P[((jl2*4+2)*4+g)*8+b] + P[((jl2*4+3)*4+g)*8+b];
                        float gi = gv[0] + bl0[j2], gf = gv[1] + bl0[j2 + 1024];
                        float gg = gv[2] + bl0[j2 + 2048], go = gv[3] + bl0[j2 + 3072];
                        int idx = b * DRNN + j2;
                        float co = g_c0[ep][idx], ho = g_h0[ep][idx];
                        float cn = sigm(gf) * co + sigm(gi) * tanh_f(gg);
                        float hn = sigm(go) * tanh_f(cn);
                        float hmix = 0.9f * hn + 0.1f * ho;
                        g_c0[ep ^ 1][idx] = 0.9f * cn + 0.1f * co;
                        g_h0[ep ^ 1][idx] = hmix;
                        h0s[jl2 * 8 + b] = hmix;
                    }
                    __syncthreads();
                    if (tid < 128) {
                        int a = tid;
                        float4 wq = *(const float4*)(Wq + (size_t)a * DRNN + u * 4);
                        const float* h0s = sm + OFF_H0S;
                        #pragma unroll
                        for (int b = 0; b < 8; b++) {
                            float sq = wq.x*h0s[0*8+b] + wq.y*h0s[1*8+b]
                                     + wq.z*h0s[2*8+b] + wq.w*h0s[3*8+b];
                            g_qp[u * 1024 + b * 128 + a] = sq;
                        }
                    }
                    __syncthreads();
                }
            }
            group_sync(&g_bar1_count, &g_bar1_gen, N1);
            if (bid == 0 && tid == 0) {
                __threadfence();
                atomicExch(&g_c_done, (unsigned)(s + 1));
            }
        }
    } else {
        // ================= CHAIN 2: E(k) + out/stop(k) =================
        const int kb = bid - N1;   // 0..63
        for (int k = 0; k < TDEC; k++) {
            wait_ge(&g_c_done, (unsigned)(k + 1));
            // stage x = [h0 (buf (k+1)&1) | h1 (buf k&1)]
            float* xs = sm;
            float4* xs4 = (float4*)xs;
            const float4* h0_4 = (const float4*)(g_h0[(k + 1) & 1]);
            const float4* h1_4 = (const float4*)(g_h1[k & 1]);
            for (int i = tid; i < 4096; i += 512) {
                int b = i >> 9, o = i & 511;
                xs4[i] = (o < 256) ? h0_4[b * 256 + o] : h1_4[b * 256 + (o - 256)];
            }
            __syncthreads();
            #pragma unroll
            for (int ne = 0; ne < 4; ne++) {
                int u = kb + ne * 64;
                int jl = w >> 2, q = w & 3;
                int j = u * 4 + jl;
                const float* base = (q < 2) ? Wi1 : Wh1;
                int koff = (q < 2) ? q * 512 : (q - 2) * 512;
                const float4* w0 = (const float4*)(base + (size_t)(0 * 1024 + j) * 1024 + koff);
                const float4* w1 = (const float4*)(base + (size_t)(1 * 1024 + j) * 1024 + koff);
                const float4* w2 = (const float4*)(base + (size_t)(2 * 1024 + j) * 1024 + koff);
                const float4* w3 = (const float4*)(base + (size_t)(3 * 1024 + j) * 1024 + koff);
                int xo_base = q * 512;
                float acc[4][8];
                #pragma unroll
                for (int g = 0; g < 4; g++)
                    #pragma unroll
                    for (int b = 0; b < 8; b++) acc[g][b] = 0.f;
                #pragma unroll 2
                for (int it = 0; it < 4; it++) {
                    float4 wv0 = w0[it * 32 + ln];
                    float4 wv1 = w1[it * 32 + ln];
                    float4 wv2 = w2[it * 32 + ln];
                    float4 wv3 = w3[it * 32 + ln];
                    int xo = xo_base + it * 128 + ln * 4;
                    #pragma unroll
                    for (int b = 0; b < 8; b++) {
                        float4 xv = *(const float4*)(xs + b * 2048 + xo);
                        acc[0][b] += wv0.x*xv.x + wv0.y*xv.y + wv0.z*xv.z + wv0.w*xv.w;
                        acc[1][b] += wv1.x*xv.x + wv1.y*xv.y + wv1.z*xv.z + wv1.w*xv.w;
                        acc[2][b] += wv2.x*xv.x + wv2.y*xv.y + wv2.z*xv.z + wv2.w*xv.w;
                        acc[3][b] += wv3.x*xv.x + wv3.y*xv.y + wv3.z*xv.z + wv3.w*xv.w;
                    }
                }
                float* P = sm + OFF_P;
                #pragma unroll
                for (int g = 0; g < 4; g++)
                    #pragma unroll
                    for (int b = 0; b < 8; b++) {
                        float v = warp_sum(acc[g][b]);
                        if (ln == 0) P[(w * 4 + g) * 8 + b] = v;
                    }
                __syncthreads();
                if (tid < 32) {
                    int jl2 = tid >> 3, b = tid & 7, j2 = u * 4 + jl2;
                    float gv[4];
                    #pragma unroll
                    for (int g = 0; g < 4; g++)
                        gv[g] = P[((jl2*4+0)*4+g)*8+b] + P[((jl2*4+1)*4+g)*8+b]
                              + P[((jl2*4+2)*4+g)*8+b] + P[((jl2*4+3)*4+g)*8+b];
                    float gi = gv[0] + bl1[j2], gf = gv[1] + bl1[j2 + 1024];
                    float gg = gv[2] + bl1[j2 + 2048], go = gv[3] + bl1[j2 + 3072];
                    int idx = b * DRNN + j2;
                    float co = g_c1[k & 1][idx], ho = g_h1[k & 1][idx];
                    float cn = sigm(gf) * co + sigm(gi) * tanh_f(gg);
                    float hn = sigm(go) * tanh_f(cn);
                    g_c1[(k + 1) & 1][idx] = 0.9f * cn + 0.1f * co;
                    g_h1[(k + 1) & 1][idx] = 0.9f * hn + 0.1f * ho;
                }
                __syncthreads();
            }
            group_sync(&g_bar2_count, &g_bar2_gen, N2);
            if (bid == N1 && tid == 0) {
                __threadfence();
                atomicExch(&g_e_done, (unsigned)(k + 1));
            }
            {
                int u = kb * 16 + w;
                if (u < (ODIM + 1) * BB)
                    outstop_warp(u >> 3, u & 7, k, (k + 1) & 1, ln, featW, stopW, stopb, out);
            }
        }
    }
}

extern "C" void kernel_launch(void* const* d_in, const int* in_sizes, int n_in,
                              void* d_out, int out_size) {
    const float* mem   = (const float*)d_in[0];
    const int*   mlen  = (const int*)  d_in[1];
    const float* tgt   = (const float*)d_in[2];
    const float* Wmem  = (const float*)d_in[3];
    const float* Wq    = (const float*)d_in[4];
    const float* Wloc  = (const float*)d_in[5];
    const float* filt  = (const float*)d_in[6];
    const float* av    = (const float*)d_in[7];
    const float* ab    = (const float*)d_in[8];
    const float* pW1   = (const float*)d_in[9];
    const float* pb1   = (const float*)d_in[10];
    const float* pW2   = (const float*)d_in[11];
    const float* pb2   = (const float*)d_in[12];
    const float* Wi0   = (const float*)d_in[13];
    const float* Wh0   = (const float*)d_in[14];
    const float* bl0   = (const float*)d_in[15];
    const float* Wi1   = (const float*)d_in[16];
    const float* Wh1   = (const float*)d_in[17];
    const float* bl1   = (const float*)d_in[18];
    const float* featW = (const float*)d_in[19];
    const float* stopW = (const float*)d_in[20];
    const float* stopb = (const float*)d_in[21];
    float* out = (float*)d_out;

    static bool attr_set = false;
    if (!attr_set) {
        cudaFuncSetAttribute(decoder_persistent,
                             cudaFuncAttributeMaxDynamicSharedMemorySize,
                             SMEM_FLOATS * 4);
        attr_set = true;
    }

    init_kernel<<<1024, 256>>>();
    pm_kernel<<<512, 256>>>(mem, Wmem);
    prenet_kernel<<<BB * TDEC, 256>>>(tgt, pW1, pb1, pW2, pb2);
    decoder_persistent<<<N1 + N2, 512, SMEM_FLOATS * 4>>>(
        mem, mlen, Wq, Wloc, filt, av, ab,
        Wi0, Wh0, bl0, Wi1, Wh1, bl1, featW, stopW, stopb, out);
}